// round 12
// baseline (speedup 1.0000x reference)
#include <cuda_runtime.h>
#include <cuda_bf16.h>
#include <cstdint>

#define NB 64
#define NT 4096
#define KP 67
#define ND 256
#define NC 7
#define THREADS 320        // 10 warps
#define NWARPS (THREADS / 32)
#define NSTEPS 9           // 9 k-steps of 16 -> K=144 (134 live + zero pad)
#define KBPAD 152          // bf16 W row stride -> LDSM conflict-free (304B = 19*16B)
#define UROWS 16           // rows per warp unit

__device__ float g_pooled[NB * ND];          // .bss zero; self-restored each run
__device__ int   g_counter;                  // .bss zero; self-restored each run
__device__ int   g_len[NB];
__device__ int   g_prefix[NB + 1];
__device__ __nv_bfloat16 g_wt_hi[ND * KBPAD];
__device__ __nv_bfloat16 g_wt_lo[ND * KBPAD];

// smem map (bytes)
#define SW_HI   0
#define SW_LO   (ND * KBPAD * 2)                 // 77824
#define SP_OFF  (2 * ND * KBPAD * 2)             // 155648: prefix[65] + len[64]
#define SMEM_SZ (SP_OFF + 129 * 4)
// bn tail reuses sm[0..]: sbm[NB*ND] + sWc[ND*NC] = 72704B < SMEM_SZ

// ---- fused prologue: block 0 does length normalize + prefix; all blocks do W split ----
__global__ void prologue_kernel(const void* __restrict__ lenraw,
                                const float* __restrict__ W1)
{
    // W1 [134][256] -> Wt_hi/Wt_lo [256][KBPAD] bf16 (transposed, split, padded)
    int idx = blockIdx.x * 256 + threadIdx.x;
    if (idx < ND * KBPAD) {
        int n = idx / KBPAD;
        int k = idx - n * KBPAD;
        float v = (k < 2 * KP) ? W1[k * ND + n] : 0.0f;
        __nv_bfloat16 h = __float2bfloat16(v);
        __nv_bfloat16 l = __float2bfloat16(v - __bfloat162float(h));
        g_wt_hi[idx] = h;
        g_wt_lo[idx] = l;
    }

    if (blockIdx.x == 0) {
        __shared__ unsigned s_lo, s_hi;
        __shared__ int s_len[NB];
        const int i = threadIdx.x;
        if (i < 64) {
            const int*       as32 = (const int*)lenraw;
            int v32 = as32[i];
            bool ok = (v32 >= 1 && v32 <= NT);
            unsigned lo = __ballot_sync(0xffffffffu, i < 32 ? ok : true);
            unsigned hi = __ballot_sync(0xffffffffu, i >= 32 ? ok : true);
            if (i == 0)  s_lo = lo;
            if (i == 32) s_hi = hi;
        }
        __syncthreads();
        if (i < 64) {
            const int*       as32 = (const int*)lenraw;
            const long long* as64 = (const long long*)lenraw;
            bool all32 = (s_lo == 0xffffffffu) && (s_hi == 0xffffffffu);
            int len = all32 ? as32[i] : (int)as64[i];
            g_len[i] = len;
            s_len[i] = len;
        }
        __syncthreads();
        if (i == 0) {
            int acc = 0;
            for (int k = 0; k < NB; k++) { g_prefix[k] = acc; acc += (s_len[k] + UROWS - 1) / UROWS; }
            g_prefix[NB] = acc;
        }
    }
}

__device__ __forceinline__ void bsplit(float2 f, uint32_t& h, uint32_t& l)
{
    __nv_bfloat162 hh = __floats2bfloat162_rn(f.x, f.y);   // .x in low 16 bits
    float rx = f.x - __bfloat162float(hh.x);
    float ry = f.y - __bfloat162float(hh.y);
    __nv_bfloat162 ll = __floats2bfloat162_rn(rx, ry);
    h = *(uint32_t*)&hh;
    l = *(uint32_t*)&ll;
}

__device__ __forceinline__ float2 load_gated(const float* __restrict__ body,
                                             const float* __restrict__ hand_r,
                                             const float* __restrict__ hand_l,
                                             int b, int t, int j)
{
    const float* src;
    if (j < 25)       src = body   + ((size_t)b * NT + t) * 75 + 3 * j;
    else if (j < 46)  src = hand_r + ((size_t)b * NT + t) * 63 + 3 * (j - 25);
    else              src = hand_l + ((size_t)b * NT + t) * 63 + 3 * (j - 46);
    float x = src[0], y = src[1], c = src[2];
    float g = (c > 0.1f) ? 1.0f : 0.0f;
    return make_float2(x * g, y * g);
}

#define LDSM4(d0, d1, d2, d3, addr)                                              \
    asm volatile("ldmatrix.sync.aligned.m8n8.x4.shared.b16 {%0,%1,%2,%3}, [%4];" \
                 : "=r"(d0), "=r"(d1), "=r"(d2), "=r"(d3) : "r"(addr))

#define HMMA(ACC, A, B0, B1)                                                  \
    asm volatile("mma.sync.aligned.m16n8k16.row.col.f32.bf16.bf16.f32 "       \
                 "{%0,%1,%2,%3}, {%4,%5,%6,%7}, {%8,%9}, {%0,%1,%2,%3};"      \
                 : "+f"((ACC)[0]), "+f"((ACC)[1]), "+f"((ACC)[2]), "+f"((ACC)[3]) \
                 : "r"((A)[0]), "r"((A)[1]), "r"((A)[2]), "r"((A)[3]),        \
                   "r"(B0), "r"(B1))

__device__ __forceinline__ uint32_t smem_u32(const void* p) {
    uint32_t a;
    asm("{ .reg .u64 t; cvta.to.shared.u64 t, %1; cvt.u32.u64 %0, t; }" : "=r"(a) : "l"(p));
    return a;
}

__global__ __launch_bounds__(THREADS, 1)
void gemm_pool_kernel(const float* __restrict__ body,
                      const float* __restrict__ hand_r,
                      const float* __restrict__ hand_l,
                      const float* __restrict__ b1,
                      const float* __restrict__ gamma,
                      const float* __restrict__ beta,
                      const float* __restrict__ Wc,
                      const float* __restrict__ bc,
                      float* __restrict__ out)
{
    extern __shared__ char sm[];
    __nv_bfloat16* BsH = (__nv_bfloat16*)(sm + SW_HI);
    __nv_bfloat16* BsL = (__nv_bfloat16*)(sm + SW_LO);
    int* s_prefix = (int*)(sm + SP_OFF);          // [65]
    int* s_len    = s_prefix + 65;                // [64]

    const int tid = threadIdx.x;
    const int wid = tid >> 5;
    const int lid = tid & 31;
    const int g   = lid >> 2;          // 0..7  (output row group)
    const int t   = lid & 3;           // 0..3  (k pair)
    const int mid  = lid >> 3;         // ldmatrix matrix id
    const int lrow = lid & 7;          // ldmatrix row within matrix

    // ---- one-time: W hi/lo into smem; prefix+len into smem ----
    {
        const uint4* sh = (const uint4*)g_wt_hi;
        const uint4* sl = (const uint4*)g_wt_lo;
        uint4* dh = (uint4*)BsH;
        uint4* dl = (uint4*)BsL;
        const int n16 = ND * KBPAD * 2 / 16;      // 4864
        for (int i = tid; i < n16; i += THREADS) { dh[i] = sh[i]; dl[i] = sl[i]; }
        if (tid < 65) s_prefix[tid] = g_prefix[tid];
        if (tid < 64) s_len[tid] = g_len[tid];
    }
    __syncthreads();

    const int total_units = s_prefix[NB];
    const int gwarp   = blockIdx.x * NWARPS + wid;
    const int gstride = gridDim.x * NWARPS;
    const unsigned gmask = 0x11111111u << t;       // lanes sharing this t (8 g-groups)

    // per-lane ldmatrix element offset within a 16-row W block
    const uint32_t lane_b_elem = (uint32_t)(((mid >> 1) * 8 + lrow) * KBPAD + (mid & 1) * 8);
    const uint32_t baseH = smem_u32(BsH) + lane_b_elem * 2;
    const uint32_t baseL = smem_u32(BsL) + lane_b_elem * 2;

    #pragma unroll 1
    for (int u = gwarp; u < total_units; u += gstride) {
        int b = 0;
        #pragma unroll
        for (int step = 32; step; step >>= 1)
            if (s_prefix[b + step] <= u) b += step;
        const int t0  = (u - s_prefix[b]) * UROWS;
        const int len = s_len[b];
        const int r0  = t0 + g;
        const int r1  = r0 + 8;

        // ---- gather + gate + split A fragments straight from global ----
        uint32_t a_hi[NSTEPS][4], a_lo[NSTEPS][4];
        #pragma unroll
        for (int ks = 0; ks < NSTEPS; ks++) {
            const int j  = ks * 8 + t;
            const int j2 = j + 4;
            float2 p0 = (j  < KP) ? load_gated(body, hand_r, hand_l, b, r0, j)  : make_float2(0.f, 0.f);
            float2 p1 = (j  < KP) ? load_gated(body, hand_r, hand_l, b, r1, j)  : make_float2(0.f, 0.f);
            float2 p2 = (j2 < KP) ? load_gated(body, hand_r, hand_l, b, r0, j2) : make_float2(0.f, 0.f);
            float2 p3 = (j2 < KP) ? load_gated(body, hand_r, hand_l, b, r1, j2) : make_float2(0.f, 0.f);
            bsplit(p0, a_hi[ks][0], a_lo[ks][0]);
            bsplit(p1, a_hi[ks][1], a_lo[ks][1]);
            bsplit(p2, a_hi[ks][2], a_lo[ks][2]);
            bsplit(p3, a_hi[ks][3], a_lo[ks][3]);
        }

        const bool v0 = r0 < len;
        const bool v1 = r1 < len;

        #pragma unroll 1
        for (int half = 0; half < 2; half++) {
            const int base_n = half * 128;
            float acc[16][4];
            #pragma unroll
            for (int nt = 0; nt < 16; nt++)
                #pragma unroll
                for (int q = 0; q < 4; q++) acc[nt][q] = 0.0f;

            #pragma unroll
            for (int ks = 0; ks < NSTEPS; ks++) {
                #pragma unroll
                for (int ntp = 0; ntp < 8; ntp++) {
                    const uint32_t off = (uint32_t)(((base_n + ntp * 16) * KBPAD + ks * 16) * 2);
                    uint32_t bh0, bh1, bh2, bh3, bl0, bl1, bl2, bl3;
                    LDSM4(bh0, bh1, bh2, bh3, baseH + off);
                    LDSM4(bl0, bl1, bl2, bl3, baseL + off);
                    // Ah*Wh + Ah*Wl + Al*Wh (drop Al*Wl)
                    HMMA(acc[2 * ntp],     a_hi[ks], bh0, bh1);
                    HMMA(acc[2 * ntp + 1], a_hi[ks], bh2, bh3);
                    HMMA(acc[2 * ntp],     a_hi[ks], bl0, bl1);
                    HMMA(acc[2 * ntp + 1], a_hi[ks], bl2, bl3);
                    HMMA(acc[2 * ntp],     a_lo[ks], bh0, bh1);
                    HMMA(acc[2 * ntp + 1], a_lo[ks], bh2, bh3);
                }
            }

            // ---- bias + relu + mask + partitioned redux-max + REDG ----
            #pragma unroll
            for (int nt = 0; nt < 16; nt++) {
                const int col = base_n + nt * 8 + 2 * t;
                float bb0 = __ldg(&b1[col]);
                float bb1 = __ldg(&b1[col + 1]);
                float m0v = fmaxf(v0 ? fmaxf(acc[nt][0] + bb0, 0.0f) : 0.0f,
                                  v1 ? fmaxf(acc[nt][2] + bb0, 0.0f) : 0.0f);
                float m1v = fmaxf(v0 ? fmaxf(acc[nt][1] + bb1, 0.0f) : 0.0f,
                                  v1 ? fmaxf(acc[nt][3] + bb1, 0.0f) : 0.0f);
                unsigned r0u = __reduce_max_sync(gmask, __float_as_uint(m0v));
                unsigned r1u = __reduce_max_sync(gmask, __float_as_uint(m1v));
                if (g == 0) {
                    atomicMax((int*)&g_pooled[b * ND + col],     (int)r0u);
                    atomicMax((int*)&g_pooled[b * ND + col + 1], (int)r1u);
                }
            }
        }
    }

    // ---- completion counter: last CTA runs BN + classifier, then restores state ----
    __shared__ int s_last;
    __syncthreads();
    __threadfence();
    if (tid == 0)
        s_last = (atomicAdd(&g_counter, 1) == (int)gridDim.x - 1) ? 1 : 0;
    __syncthreads();
    if (!s_last) return;
    __threadfence();

    {
        float* sbm = (float*)sm;            // [NB][ND]
        float* sWc = sbm + NB * ND;         // [ND][NC]
        for (int i = tid; i < ND * NC; i += THREADS) sWc[i] = Wc[i];

        if (tid < ND) {
            const int d = tid;
            float v[NB];
            float s = 0.f;
            #pragma unroll
            for (int bb = 0; bb < NB; bb++) { v[bb] = g_pooled[bb * ND + d]; s += v[bb]; }
            float mean = s * (1.0f / NB);
            float q = 0.f;
            #pragma unroll
            for (int bb = 0; bb < NB; bb++) { float tt = v[bb] - mean; q += tt * tt; }
            float rstd = rsqrtf(q * (1.0f / NB) + 1e-5f);
            float ga = gamma[d], be = beta[d];
            #pragma unroll
            for (int bb = 0; bb < NB; bb++) sbm[bb * ND + d] = (v[bb] - mean) * rstd * ga + be;
        }
        __syncthreads();

        for (int idx = tid; idx < NB * NC; idx += THREADS) {
            int bb = idx / NC, c = idx - bb * NC;
            float sum = bc[c];
            const float* row = &sbm[bb * ND];
            #pragma unroll 8
            for (int dd = 0; dd < ND; dd++) sum += row[dd] * sWc[dd * NC + c];
            out[bb * NC + c] = sum;
        }

        // restore zeroed invariant for the next graph replay
        for (int i = tid; i < NB * ND; i += THREADS) g_pooled[i] = 0.0f;
        if (tid == 0) g_counter = 0;
    }
}

extern "C" void kernel_launch(void* const* d_in, const int* in_sizes, int n_in,
                              void* d_out, int out_size)
{
    const float* body   = (const float*)d_in[0];
    const float* hand_r = (const float*)d_in[1];
    const float* hand_l = (const float*)d_in[2];
    const void*  length = d_in[3];
    const float* W1     = (const float*)d_in[4];
    const float* b1     = (const float*)d_in[5];
    const float* gamma  = (const float*)d_in[6];
    const float* beta   = (const float*)d_in[7];
    const float* Wc     = (const float*)d_in[8];
    const float* bc     = (const float*)d_in[9];
    float* out = (float*)d_out;

    int nsm = 148;
    cudaDeviceGetAttribute(&nsm, cudaDevAttrMultiProcessorCount, 0);

    cudaFuncSetAttribute(gemm_pool_kernel,
                         cudaFuncAttributeMaxDynamicSharedMemorySize, SMEM_SZ);

    prologue_kernel<<<(ND * KBPAD + 255) / 256, 256>>>(length, W1);
    gemm_pool_kernel<<<nsm, THREADS, SMEM_SZ>>>(body, hand_r, hand_l, b1,
                                                gamma, beta, Wc, bc, out);
}

// round 16
// speedup vs baseline: 1.0265x; 1.0265x over previous
#include <cuda_runtime.h>
#include <cuda_bf16.h>
#include <cstdint>

#define NB 64
#define NT 4096
#define KP 67
#define ND 256
#define NC 7
#define THREADS 256        // 8 warps: reg cap 256/thread -> no spills (R12 lesson)
#define NWARPS (THREADS / 32)
#define NSTEPS 9           // 9 k-steps of 16 -> K=144 (134 live + zero pad)
#define KBPAD 152          // bf16 W row stride -> LDSM conflict-free (304B = 19*16B)
#define UROWS 16           // rows per warp unit

__device__ float g_pooled[NB * ND];          // .bss zero; self-restored each run
__device__ int   g_counter;                  // .bss zero; self-restored each run
__device__ int   g_len[NB];
__device__ int   g_prefix[NB + 1];
__device__ __nv_bfloat16 g_wt_hi[ND * KBPAD];
__device__ __nv_bfloat16 g_wt_lo[ND * KBPAD];

// smem map (bytes)
#define SW_HI   0
#define SW_LO   (ND * KBPAD * 2)                 // 77824
#define SP_OFF  (2 * ND * KBPAD * 2)             // 155648: prefix[65] + len[64]
#define SMEM_SZ (SP_OFF + 129 * 4)
// bn tail reuses sm[0..]: sbm[NB*ND] + sWc[ND*NC] = 72704B < SMEM_SZ

// ---- fused prologue: block 0 does length normalize + prefix; all blocks do W split ----
__global__ void prologue_kernel(const void* __restrict__ lenraw,
                                const float* __restrict__ W1)
{
    int idx = blockIdx.x * 256 + threadIdx.x;
    if (idx < ND * KBPAD) {
        int n = idx / KBPAD;
        int k = idx - n * KBPAD;
        float v = (k < 2 * KP) ? W1[k * ND + n] : 0.0f;
        __nv_bfloat16 h = __float2bfloat16(v);
        __nv_bfloat16 l = __float2bfloat16(v - __bfloat162float(h));
        g_wt_hi[idx] = h;
        g_wt_lo[idx] = l;
    }

    if (blockIdx.x == 0) {
        __shared__ unsigned s_lo, s_hi;
        __shared__ int s_len[NB];
        const int i = threadIdx.x;
        if (i < 64) {
            const int* as32 = (const int*)lenraw;
            int v32 = as32[i];
            bool ok = (v32 >= 1 && v32 <= NT);
            unsigned lo = __ballot_sync(0xffffffffu, i < 32 ? ok : true);
            unsigned hi = __ballot_sync(0xffffffffu, i >= 32 ? ok : true);
            if (i == 0)  s_lo = lo;
            if (i == 32) s_hi = hi;
        }
        __syncthreads();
        if (i < 64) {
            const int*       as32 = (const int*)lenraw;
            const long long* as64 = (const long long*)lenraw;
            bool all32 = (s_lo == 0xffffffffu) && (s_hi == 0xffffffffu);
            int len = all32 ? as32[i] : (int)as64[i];
            g_len[i] = len;
            s_len[i] = len;
        }
        __syncthreads();
        if (i == 0) {
            int acc = 0;
            for (int k = 0; k < NB; k++) { g_prefix[k] = acc; acc += (s_len[k] + UROWS - 1) / UROWS; }
            g_prefix[NB] = acc;
        }
    }
}

__device__ __forceinline__ void bsplit(float2 f, uint32_t& h, uint32_t& l)
{
    __nv_bfloat162 hh = __floats2bfloat162_rn(f.x, f.y);   // .x in low 16 bits
    float rx = f.x - __bfloat162float(hh.x);
    float ry = f.y - __bfloat162float(hh.y);
    __nv_bfloat162 ll = __floats2bfloat162_rn(rx, ry);
    h = *(uint32_t*)&hh;
    l = *(uint32_t*)&ll;
}

__device__ __forceinline__ float2 load_gated(const float* __restrict__ body,
                                             const float* __restrict__ hand_r,
                                             const float* __restrict__ hand_l,
                                             int b, int t, int j)
{
    const float* src;
    if (j < 25)       src = body   + ((size_t)b * NT + t) * 75 + 3 * j;
    else if (j < 46)  src = hand_r + ((size_t)b * NT + t) * 63 + 3 * (j - 25);
    else              src = hand_l + ((size_t)b * NT + t) * 63 + 3 * (j - 46);
    float x = src[0], y = src[1], c = src[2];
    float g = (c > 0.1f) ? 1.0f : 0.0f;
    return make_float2(x * g, y * g);
}

#define LDSM4(d0, d1, d2, d3, addr)                                              \
    asm volatile("ldmatrix.sync.aligned.m8n8.x4.shared.b16 {%0,%1,%2,%3}, [%4];" \
                 : "=r"(d0), "=r"(d1), "=r"(d2), "=r"(d3) : "r"(addr))

#define HMMA(ACC, A, B0, B1)                                                  \
    asm volatile("mma.sync.aligned.m16n8k16.row.col.f32.bf16.bf16.f32 "       \
                 "{%0,%1,%2,%3}, {%4,%5,%6,%7}, {%8,%9}, {%0,%1,%2,%3};"      \
                 : "+f"((ACC)[0]), "+f"((ACC)[1]), "+f"((ACC)[2]), "+f"((ACC)[3]) \
                 : "r"((A)[0]), "r"((A)[1]), "r"((A)[2]), "r"((A)[3]),        \
                   "r"(B0), "r"(B1))

__device__ __forceinline__ uint32_t smem_u32(const void* p) {
    uint32_t a;
    asm("{ .reg .u64 t; cvta.to.shared.u64 t, %1; cvt.u32.u64 %0, t; }" : "=r"(a) : "l"(p));
    return a;
}

__global__ __launch_bounds__(THREADS, 1)
void gemm_pool_kernel(const float* __restrict__ body,
                      const float* __restrict__ hand_r,
                      const float* __restrict__ hand_l,
                      const float* __restrict__ b1,
                      const float* __restrict__ gamma,
                      const float* __restrict__ beta,
                      const float* __restrict__ Wc,
                      const float* __restrict__ bc,
                      float* __restrict__ out)
{
    extern __shared__ char sm[];
    __nv_bfloat16* BsH = (__nv_bfloat16*)(sm + SW_HI);
    __nv_bfloat16* BsL = (__nv_bfloat16*)(sm + SW_LO);
    int* s_prefix = (int*)(sm + SP_OFF);          // [65]
    int* s_len    = s_prefix + 65;                // [64]

    const int tid = threadIdx.x;
    const int wid = tid >> 5;
    const int lid = tid & 31;
    const int g   = lid >> 2;          // 0..7  (output row group)
    const int t   = lid & 3;           // 0..3  (k pair)
    const int mid  = lid >> 3;         // ldmatrix matrix id
    const int lrow = lid & 7;          // ldmatrix row within matrix

    // ---- one-time: W hi/lo into smem; prefix+len into smem ----
    {
        const uint4* sh = (const uint4*)g_wt_hi;
        const uint4* sl = (const uint4*)g_wt_lo;
        uint4* dh = (uint4*)BsH;
        uint4* dl = (uint4*)BsL;
        const int n16 = ND * KBPAD * 2 / 16;      // 4864
        for (int i = tid; i < n16; i += THREADS) { dh[i] = sh[i]; dl[i] = sl[i]; }
        if (tid < 65) s_prefix[tid] = g_prefix[tid];
        if (tid < 64) s_len[tid] = g_len[tid];
    }
    __syncthreads();

    const int total_units = s_prefix[NB];
    const int gwarp   = blockIdx.x * NWARPS + wid;
    const int gstride = gridDim.x * NWARPS;
    const unsigned gmask = 0x11111111u << t;       // lanes sharing this t (8 g-groups)

    // per-lane ldmatrix element offset within a 16-row W block
    const uint32_t lane_b_elem = (uint32_t)(((mid >> 1) * 8 + lrow) * KBPAD + (mid & 1) * 8);
    const uint32_t baseH = smem_u32(BsH) + lane_b_elem * 2;
    const uint32_t baseL = smem_u32(BsL) + lane_b_elem * 2;

    #pragma unroll 1
    for (int u = gwarp; u < total_units; u += gstride) {
        int b = 0;
        #pragma unroll
        for (int step = 32; step; step >>= 1)
            if (s_prefix[b + step] <= u) b += step;
        const int t0  = (u - s_prefix[b]) * UROWS;
        const int len = s_len[b];
        const int r0  = t0 + g;
        const int r1  = r0 + 8;

        // ---- gather + gate + split A fragments straight from global ----
        uint32_t a_hi[NSTEPS][4], a_lo[NSTEPS][4];
        #pragma unroll
        for (int ks = 0; ks < NSTEPS; ks++) {
            const int j  = ks * 8 + t;
            const int j2 = j + 4;
            float2 p0 = (j  < KP) ? load_gated(body, hand_r, hand_l, b, r0, j)  : make_float2(0.f, 0.f);
            float2 p1 = (j  < KP) ? load_gated(body, hand_r, hand_l, b, r1, j)  : make_float2(0.f, 0.f);
            float2 p2 = (j2 < KP) ? load_gated(body, hand_r, hand_l, b, r0, j2) : make_float2(0.f, 0.f);
            float2 p3 = (j2 < KP) ? load_gated(body, hand_r, hand_l, b, r1, j2) : make_float2(0.f, 0.f);
            bsplit(p0, a_hi[ks][0], a_lo[ks][0]);
            bsplit(p1, a_hi[ks][1], a_lo[ks][1]);
            bsplit(p2, a_hi[ks][2], a_lo[ks][2]);
            bsplit(p3, a_hi[ks][3], a_lo[ks][3]);
        }

        const bool v0 = r0 < len;
        const bool v1 = r1 < len;

        #pragma unroll 1
        for (int half = 0; half < 2; half++) {
            const int base_n = half * 128;
            float acc[16][4];
            #pragma unroll
            for (int nt = 0; nt < 16; nt++)
                #pragma unroll
                for (int q = 0; q < 4; q++) acc[nt][q] = 0.0f;

            #pragma unroll
            for (int ks = 0; ks < NSTEPS; ks++) {
                #pragma unroll
                for (int ntp = 0; ntp < 8; ntp++) {
                    const uint32_t off = (uint32_t)(((base_n + ntp * 16) * KBPAD + ks * 16) * 2);
                    uint32_t bh0, bh1, bh2, bh3, bl0, bl1, bl2, bl3;
                    LDSM4(bh0, bh1, bh2, bh3, baseH + off);
                    LDSM4(bl0, bl1, bl2, bl3, baseL + off);
                    // Ah*Wh + Ah*Wl + Al*Wh (drop Al*Wl)
                    HMMA(acc[2 * ntp],     a_hi[ks], bh0, bh1);
                    HMMA(acc[2 * ntp + 1], a_hi[ks], bh2, bh3);
                    HMMA(acc[2 * ntp],     a_hi[ks], bl0, bl1);
                    HMMA(acc[2 * ntp + 1], a_hi[ks], bl2, bl3);
                    HMMA(acc[2 * ntp],     a_lo[ks], bh0, bh1);
                    HMMA(acc[2 * ntp + 1], a_lo[ks], bh2, bh3);
                }
            }

            // ---- bias + relu + mask + partitioned redux-max + atomicMax ----
            #pragma unroll
            for (int nt = 0; nt < 16; nt++) {
                const int col = base_n + nt * 8 + 2 * t;
                float bb0 = __ldg(&b1[col]);
                float bb1 = __ldg(&b1[col + 1]);
                float m0v = fmaxf(v0 ? fmaxf(acc[nt][0] + bb0, 0.0f) : 0.0f,
                                  v1 ? fmaxf(acc[nt][2] + bb0, 0.0f) : 0.0f);
                float m1v = fmaxf(v0 ? fmaxf(acc[nt][1] + bb1, 0.0f) : 0.0f,
                                  v1 ? fmaxf(acc[nt][3] + bb1, 0.0f) : 0.0f);
                unsigned r0u = __reduce_max_sync(gmask, __float_as_uint(m0v));
                unsigned r1u = __reduce_max_sync(gmask, __float_as_uint(m1v));
                if (g == 0) {
                    atomicMax((int*)&g_pooled[b * ND + col],     (int)r0u);
                    atomicMax((int*)&g_pooled[b * ND + col + 1], (int)r1u);
                }
            }
        }
    }

    // ---- completion counter: last CTA runs BN + classifier, then restores state ----
    __shared__ int s_last;
    __syncthreads();
    __threadfence();
    if (tid == 0)
        s_last = (atomicAdd(&g_counter, 1) == (int)gridDim.x - 1) ? 1 : 0;
    __syncthreads();
    if (!s_last) return;
    __threadfence();

    {
        float* sbm = (float*)sm;            // [NB][ND]
        float* sWc = sbm + NB * ND;         // [ND][NC]
        for (int i = tid; i < ND * NC; i += THREADS) sWc[i] = Wc[i];

        {
            const int d = tid;              // THREADS == ND
            float v[NB];
            float s = 0.f;
            #pragma unroll
            for (int bb = 0; bb < NB; bb++) { v[bb] = g_pooled[bb * ND + d]; s += v[bb]; }
            float mean = s * (1.0f / NB);
            float q = 0.f;
            #pragma unroll
            for (int bb = 0; bb < NB; bb++) { float tt = v[bb] - mean; q += tt * tt; }
            float rstd = rsqrtf(q * (1.0f / NB) + 1e-5f);
            float ga = gamma[d], be = beta[d];
            #pragma unroll
            for (int bb = 0; bb < NB; bb++) sbm[bb * ND + d] = (v[bb] - mean) * rstd * ga + be;
        }
        __syncthreads();

        for (int idx = tid; idx < NB * NC; idx += THREADS) {
            int bb = idx / NC, c = idx - bb * NC;
            float sum = bc[c];
            const float* row = &sbm[bb * ND];
            #pragma unroll 8
            for (int dd = 0; dd < ND; dd++) sum += row[dd] * sWc[dd * NC + c];
            out[bb * NC + c] = sum;
        }

        // restore zeroed invariant for the next graph replay
        for (int i = tid; i < NB * ND; i += THREADS) g_pooled[i] = 0.0f;
        if (tid == 0) g_counter = 0;
    }
}

extern "C" void kernel_launch(void* const* d_in, const int* in_sizes, int n_in,
                              void* d_out, int out_size)
{
    const float* body   = (const float*)d_in[0];
    const float* hand_r = (const float*)d_in[1];
    const float* hand_l = (const float*)d_in[2];
    const void*  length = d_in[3];
    const float* W1     = (const float*)d_in[4];
    const float* b1     = (const float*)d_in[5];
    const float* gamma  = (const float*)d_in[6];
    const float* beta   = (const float*)d_in[7];
    const float* Wc     = (const float*)d_in[8];
    const float* bc     = (const float*)d_in[9];
    float* out = (float*)d_out;

    int nsm = 148;
    cudaDeviceGetAttribute(&nsm, cudaDevAttrMultiProcessorCount, 0);

    cudaFuncSetAttribute(gemm_pool_kernel,
                         cudaFuncAttributeMaxDynamicSharedMemorySize, SMEM_SZ);

    prologue_kernel<<<(ND * KBPAD + 255) / 256, 256>>>(length, W1);
    gemm_pool_kernel<<<nsm, THREADS, SMEM_SZ>>>(body, hand_r, hand_l, b1,
                                                gamma, beta, Wc, bc, out);
}

// round 17
// speedup vs baseline: 2.0747x; 2.0212x over previous
#include <cuda_runtime.h>
#include <cuda_bf16.h>
#include <cstdint>

#define NB 64
#define NT 4096
#define KP 67
#define ND 256
#define NC 7
#define THREADS 256
#define NWARPS (THREADS / 32)
#define NSTEPS 9           // 9 k-steps of 16 -> K=144 (134 live + zero pad)
#define KBPAD 152          // bf16 W row stride -> LDSM conflict-free (304B = 19*16B)
#define UROWS 16           // rows per warp unit

__device__ float g_pooled[NB * ND];          // .bss zero; self-restored each run
__device__ int   g_counter;                  // .bss zero; self-restored each run
__device__ int   g_len[NB];
__device__ int   g_prefix[NB + 1];
__device__ __nv_bfloat16 g_wt_hi[ND * KBPAD];
__device__ __nv_bfloat16 g_wt_lo[ND * KBPAD];

// smem map (bytes)
#define SW_HI   0
#define SW_LO   (ND * KBPAD * 2)                 // 77824
#define SP_OFF  (2 * ND * KBPAD * 2)             // 155648: prefix[65] + len[64]
#define SMEM_SZ (SP_OFF + 129 * 4)
// bn tail reuses sm[0..]: sbm[NB*ND] + sWc[ND*NC] = 72704B < SMEM_SZ

// ---- fused prologue: block 0 does length normalize + prefix; all blocks do W split ----
__global__ void prologue_kernel(const void* __restrict__ lenraw,
                                const float* __restrict__ W1)
{
    int idx = blockIdx.x * 256 + threadIdx.x;
    if (idx < ND * KBPAD) {
        int n = idx / KBPAD;
        int k = idx - n * KBPAD;
        float v = (k < 2 * KP) ? W1[k * ND + n] : 0.0f;
        __nv_bfloat16 h = __float2bfloat16(v);
        __nv_bfloat16 l = __float2bfloat16(v - __bfloat162float(h));
        g_wt_hi[idx] = h;
        g_wt_lo[idx] = l;
    }

    if (blockIdx.x == 0) {
        __shared__ unsigned s_lo, s_hi;
        __shared__ int s_len[NB];
        const int i = threadIdx.x;
        if (i < 64) {
            const int* as32 = (const int*)lenraw;
            int v32 = as32[i];
            bool ok = (v32 >= 1 && v32 <= NT);
            unsigned lo = __ballot_sync(0xffffffffu, i < 32 ? ok : true);
            unsigned hi = __ballot_sync(0xffffffffu, i >= 32 ? ok : true);
            if (i == 0)  s_lo = lo;
            if (i == 32) s_hi = hi;
        }
        __syncthreads();
        if (i < 64) {
            const int*       as32 = (const int*)lenraw;
            const long long* as64 = (const long long*)lenraw;
            bool all32 = (s_lo == 0xffffffffu) && (s_hi == 0xffffffffu);
            int len = all32 ? as32[i] : (int)as64[i];
            g_len[i] = len;
            s_len[i] = len;
        }
        __syncthreads();
        if (i == 0) {
            int acc = 0;
            for (int k = 0; k < NB; k++) { g_prefix[k] = acc; acc += (s_len[k] + UROWS - 1) / UROWS; }
            g_prefix[NB] = acc;
        }
    }
}

__device__ __forceinline__ void bsplit(float2 f, uint32_t& h, uint32_t& l)
{
    __nv_bfloat162 hh = __floats2bfloat162_rn(f.x, f.y);   // .x in low 16 bits
    float rx = f.x - __bfloat162float(hh.x);
    float ry = f.y - __bfloat162float(hh.y);
    __nv_bfloat162 ll = __floats2bfloat162_rn(rx, ry);
    h = *(uint32_t*)&hh;
    l = *(uint32_t*)&ll;
}

__device__ __forceinline__ float2 load_gated(const float* __restrict__ body,
                                             const float* __restrict__ hand_r,
                                             const float* __restrict__ hand_l,
                                             int b, int t, int j)
{
    const float* src;
    if (j < 25)       src = body   + ((size_t)b * NT + t) * 75 + 3 * j;
    else if (j < 46)  src = hand_r + ((size_t)b * NT + t) * 63 + 3 * (j - 25);
    else              src = hand_l + ((size_t)b * NT + t) * 63 + 3 * (j - 46);
    float x = src[0], y = src[1], c = src[2];
    float g = (c > 0.1f) ? 1.0f : 0.0f;
    return make_float2(x * g, y * g);
}

#define LDSM4(d0, d1, d2, d3, addr)                                              \
    asm volatile("ldmatrix.sync.aligned.m8n8.x4.shared.b16 {%0,%1,%2,%3}, [%4];" \
                 : "=r"(d0), "=r"(d1), "=r"(d2), "=r"(d3) : "r"(addr))

#define HMMA(ACC, A, B0, B1)                                                  \
    asm volatile("mma.sync.aligned.m16n8k16.row.col.f32.bf16.bf16.f32 "       \
                 "{%0,%1,%2,%3}, {%4,%5,%6,%7}, {%8,%9}, {%0,%1,%2,%3};"      \
                 : "+f"((ACC)[0]), "+f"((ACC)[1]), "+f"((ACC)[2]), "+f"((ACC)[3]) \
                 : "r"((A)[0]), "r"((A)[1]), "r"((A)[2]), "r"((A)[3]),        \
                   "r"(B0), "r"(B1))

__device__ __forceinline__ uint32_t smem_u32(const void* p) {
    uint32_t a;
    asm("{ .reg .u64 t; cvta.to.shared.u64 t, %1; cvt.u32.u64 %0, t; }" : "=r"(a) : "l"(p));
    return a;
}

__global__ __launch_bounds__(THREADS, 1)
void gemm_pool_kernel(const float* __restrict__ body,
                      const float* __restrict__ hand_r,
                      const float* __restrict__ hand_l,
                      const float* __restrict__ b1,
                      const float* __restrict__ gamma,
                      const float* __restrict__ beta,
                      const float* __restrict__ Wc,
                      const float* __restrict__ bc,
                      float* __restrict__ out)
{
    extern __shared__ char sm[];
    __nv_bfloat16* BsH = (__nv_bfloat16*)(sm + SW_HI);
    __nv_bfloat16* BsL = (__nv_bfloat16*)(sm + SW_LO);
    int* s_prefix = (int*)(sm + SP_OFF);          // [65]
    int* s_len    = s_prefix + 65;                // [64]

    const int tid = threadIdx.x;
    const int wid = tid >> 5;
    const int lid = tid & 31;
    const int g   = lid >> 2;          // 0..7  (output row group)
    const int t   = lid & 3;           // 0..3  (k pair)
    const int mid  = lid >> 3;         // ldmatrix matrix id
    const int lrow = lid & 7;          // ldmatrix row within matrix

    // ---- one-time: W hi/lo into smem; prefix+len into smem ----
    {
        const uint4* sh = (const uint4*)g_wt_hi;
        const uint4* sl = (const uint4*)g_wt_lo;
        uint4* dh = (uint4*)BsH;
        uint4* dl = (uint4*)BsL;
        const int n16 = ND * KBPAD * 2 / 16;      // 4864
        for (int i = tid; i < n16; i += THREADS) { dh[i] = sh[i]; dl[i] = sl[i]; }
        if (tid < 65) s_prefix[tid] = g_prefix[tid];
        if (tid < 64) s_len[tid] = g_len[tid];
    }
    __syncthreads();

    const int total_units = s_prefix[NB];
    const int gwarp   = blockIdx.x * NWARPS + wid;
    const int gstride = gridDim.x * NWARPS;

    // per-lane ldmatrix element offset within a 16-row W block
    const uint32_t lane_b_elem = (uint32_t)(((mid >> 1) * 8 + lrow) * KBPAD + (mid & 1) * 8);
    const uint32_t baseH = smem_u32(BsH) + lane_b_elem * 2;
    const uint32_t baseL = smem_u32(BsL) + lane_b_elem * 2;

    #pragma unroll 1
    for (int u = gwarp; u < total_units; u += gstride) {
        int b = 0;
        #pragma unroll
        for (int step = 32; step; step >>= 1)
            if (s_prefix[b + step] <= u) b += step;
        const int t0  = (u - s_prefix[b]) * UROWS;
        const int len = s_len[b];
        const int r0  = t0 + g;
        const int r1  = r0 + 8;

        // ---- gather + gate + split A fragments straight from global ----
        uint32_t a_hi[NSTEPS][4], a_lo[NSTEPS][4];
        #pragma unroll
        for (int ks = 0; ks < NSTEPS; ks++) {
            const int j  = ks * 8 + t;
            const int j2 = j + 4;
            float2 p0 = (j  < KP) ? load_gated(body, hand_r, hand_l, b, r0, j)  : make_float2(0.f, 0.f);
            float2 p1 = (j  < KP) ? load_gated(body, hand_r, hand_l, b, r1, j)  : make_float2(0.f, 0.f);
            float2 p2 = (j2 < KP) ? load_gated(body, hand_r, hand_l, b, r0, j2) : make_float2(0.f, 0.f);
            float2 p3 = (j2 < KP) ? load_gated(body, hand_r, hand_l, b, r1, j2) : make_float2(0.f, 0.f);
            bsplit(p0, a_hi[ks][0], a_lo[ks][0]);
            bsplit(p1, a_hi[ks][1], a_lo[ks][1]);
            bsplit(p2, a_hi[ks][2], a_lo[ks][2]);
            bsplit(p3, a_hi[ks][3], a_lo[ks][3]);
        }

        const bool v0 = r0 < len;
        const bool v1 = r1 < len;

        #pragma unroll 1
        for (int half = 0; half < 2; half++) {
            const int base_n = half * 128;
            float acc[16][4];
            #pragma unroll
            for (int nt = 0; nt < 16; nt++)
                #pragma unroll
                for (int q = 0; q < 4; q++) acc[nt][q] = 0.0f;

            #pragma unroll
            for (int ks = 0; ks < NSTEPS; ks++) {
                #pragma unroll
                for (int ntp = 0; ntp < 8; ntp++) {
                    const uint32_t off = (uint32_t)(((base_n + ntp * 16) * KBPAD + ks * 16) * 2);
                    uint32_t bh0, bh1, bh2, bh3, bl0, bl1, bl2, bl3;
                    LDSM4(bh0, bh1, bh2, bh3, baseH + off);
                    LDSM4(bl0, bl1, bl2, bl3, baseL + off);
                    // Ah*Wh + Ah*Wl + Al*Wh (drop Al*Wl)
                    HMMA(acc[2 * ntp],     a_hi[ks], bh0, bh1);
                    HMMA(acc[2 * ntp + 1], a_hi[ks], bh2, bh3);
                    HMMA(acc[2 * ntp],     a_hi[ks], bl0, bl1);
                    HMMA(acc[2 * ntp + 1], a_hi[ks], bl2, bl3);
                    HMMA(acc[2 * ntp],     a_lo[ks], bh0, bh1);
                    HMMA(acc[2 * ntp + 1], a_lo[ks], bh2, bh3);
                }
            }

            // ---- bias + relu + mask + shfl-tree max (R11 epilogue: REDUX is ~690cyc, SHFL is 26) ----
            #pragma unroll
            for (int nt = 0; nt < 16; nt++) {
                const int col = base_n + nt * 8 + 2 * t;
                float bb0 = __ldg(&b1[col]);
                float bb1 = __ldg(&b1[col + 1]);
                float m0v = fmaxf(v0 ? fmaxf(acc[nt][0] + bb0, 0.0f) : 0.0f,
                                  v1 ? fmaxf(acc[nt][2] + bb0, 0.0f) : 0.0f);
                float m1v = fmaxf(v0 ? fmaxf(acc[nt][1] + bb1, 0.0f) : 0.0f,
                                  v1 ? fmaxf(acc[nt][3] + bb1, 0.0f) : 0.0f);
                #pragma unroll
                for (int mk = 4; mk <= 16; mk <<= 1) {
                    m0v = fmaxf(m0v, __shfl_xor_sync(0xffffffffu, m0v, mk));
                    m1v = fmaxf(m1v, __shfl_xor_sync(0xffffffffu, m1v, mk));
                }
                if (lid < 4) {
                    atomicMax((int*)&g_pooled[b * ND + col],     __float_as_int(m0v));
                    atomicMax((int*)&g_pooled[b * ND + col + 1], __float_as_int(m1v));
                }
            }
        }
    }

    // ---- completion counter: last CTA runs BN + classifier, then restores state ----
    __shared__ int s_last;
    __syncthreads();
    __threadfence();
    if (tid == 0)
        s_last = (atomicAdd(&g_counter, 1) == (int)gridDim.x - 1) ? 1 : 0;
    __syncthreads();
    if (!s_last) return;
    __threadfence();

    {
        float* sbm = (float*)sm;            // [NB][ND]
        float* sWc = sbm + NB * ND;         // [ND][NC]
        for (int i = tid; i < ND * NC; i += THREADS) sWc[i] = Wc[i];

        {
            const int d = tid;              // THREADS == ND
            float v[NB];
            float s = 0.f;
            #pragma unroll
            for (int bb = 0; bb < NB; bb++) { v[bb] = g_pooled[bb * ND + d]; s += v[bb]; }
            float mean = s * (1.0f / NB);
            float q = 0.f;
            #pragma unroll
            for (int bb = 0; bb < NB; bb++) { float tt = v[bb] - mean; q += tt * tt; }
            float rstd = rsqrtf(q * (1.0f / NB) + 1e-5f);
            float ga = gamma[d], be = beta[d];
            #pragma unroll
            for (int bb = 0; bb < NB; bb++) sbm[bb * ND + d] = (v[bb] - mean) * rstd * ga + be;
        }
        __syncthreads();

        for (int idx = tid; idx < NB * NC; idx += THREADS) {
            int bb = idx / NC, c = idx - bb * NC;
            float sum = bc[c];
            const float* row = &sbm[bb * ND];
            #pragma unroll 8
            for (int dd = 0; dd < ND; dd++) sum += row[dd] * sWc[dd * NC + c];
            out[bb * NC + c] = sum;
        }

        // restore zeroed invariant for the next graph replay
        for (int i = tid; i < NB * ND; i += THREADS) g_pooled[i] = 0.0f;
        if (tid == 0) g_counter = 0;
    }
}

extern "C" void kernel_launch(void* const* d_in, const int* in_sizes, int n_in,
                              void* d_out, int out_size)
{
    const float* body   = (const float*)d_in[0];
    const float* hand_r = (const float*)d_in[1];
    const float* hand_l = (const float*)d_in[2];
    const void*  length = d_in[3];
    const float* W1     = (const float*)d_in[4];
    const float* b1     = (const float*)d_in[5];
    const float* gamma  = (const float*)d_in[6];
    const float* beta   = (const float*)d_in[7];
    const float* Wc     = (const float*)d_in[8];
    const float* bc     = (const float*)d_in[9];
    float* out = (float*)d_out;

    int nsm = 148;
    cudaDeviceGetAttribute(&nsm, cudaDevAttrMultiProcessorCount, 0);

    cudaFuncSetAttribute(gemm_pool_kernel,
                         cudaFuncAttributeMaxDynamicSharedMemorySize, SMEM_SZ);

    prologue_kernel<<<(ND * KBPAD + 255) / 256, 256>>>(length, W1);
    gemm_pool_kernel<<<nsm, THREADS, SMEM_SZ>>>(body, hand_r, hand_l, b1,
                                                gamma, beta, Wc, bc, out);
}